// round 1
// baseline (speedup 1.0000x reference)
#include <cuda_runtime.h>
#include <cstdint>

// LinearAttention: n=4, L=8192, h=8, d=m=64
// out[n,h,l,m] = z_l * sum_d phi(q[l,d]) * KV[d,m],  KV[d,m] = sum_s phi(k[s,d]) v[s,m]
// z_l = 1/(sum_d phi(q[l,d]) * ksum[d] + 1e-6),      ksum[d] = sum_s phi(k[s,d])
// phi(x) = elu(x * 64^-0.25) + 1  ==  (t>0 ? t+1 : exp(t)), t = x*temp

#define NB   4
#define LL   8192
#define NH   8
#define DD   64
#define NPAIR (NB*NH)          // 32
#define SPL  16                // L-splits in reduction kernel
#define CHUNK (LL/SPL)         // 512
#define UROW 8                 // s-rows per smem round

__device__ float g_kv[NPAIR * DD * DD];   // [pair][d][m]
__device__ float g_ksum[NPAIR * DD];      // [pair][d]

__device__ __forceinline__ float phi(float x) {
    x *= 0.35355339059327378f;           // 64^-0.25 = 2^-1.5
    return x > 0.f ? x + 1.f : __expf(x);
}

typedef unsigned long long u64;

__device__ __forceinline__ u64 pk2(float a) {          // {a, a}
    u64 r; asm("mov.b64 %0, {%1,%2};" : "=l"(r) : "f"(a), "f"(a)); return r;
}
__device__ __forceinline__ void fma2(u64& d, u64 a, u64 b) {
    asm("fma.rn.f32x2 %0, %1, %2, %0;" : "+l"(d) : "l"(a), "l"(b));
}
__device__ __forceinline__ void unpk(u64 v, float& lo, float& hi) {
    asm("mov.b64 {%0,%1}, %2;" : "=f"(lo), "=f"(hi) : "l"(v));
}

// ---------------------------------------------------------------------------
__global__ void zero_scratch() {
    int i = blockIdx.x * blockDim.x + threadIdx.x;
    if (i < NPAIR * DD * DD) g_kv[i] = 0.f;
    if (i < NPAIR * DD)      g_ksum[i] = 0.f;
}

// ---------------------------------------------------------------------------
// Kernel 1: KV[d][m] += phi(k)[d]*v[m], ksum[d] += phi(k)[d]
// grid (SPL, NPAIR), 256 threads. Thread tile: 4 d (packed as 2 f32x2) x 4 m.
__global__ __launch_bounds__(256, 4)
void kv_kernel(const float* __restrict__ K, const float* __restrict__ V) {
    __shared__ __align__(16) float ks[UROW][DD];
    __shared__ __align__(16) float vs[UROW][DD];

    const int pair = blockIdx.y;
    const int b = pair >> 3, hh = pair & 7;
    const int s0 = blockIdx.x * CHUNK;
    const int tid = threadIdx.x;
    const int tx = tid & 15;          // d-group: d0 = tx*4
    const int ty = tid >> 4;          // m-group: m0 = ty*4

    const size_t base = ((size_t)b * LL * NH + hh) * DD;   // + s*NH*DD

    // loader mapping: row = tid>>5 (0..7), qd = tid&31 (16 k-float4 + 16 v-float4)
    const int lrow = tid >> 5;
    const int lqd  = tid & 31;
    const bool isK = lqd < 16;
    const int lcol = (isK ? lqd : lqd - 16) * 4;

    u64 acc[4][2];
    #pragma unroll
    for (int j = 0; j < 4; j++) { acc[j][0] = 0ull; acc[j][1] = 0ull; }
    float ksa0 = 0.f, ksa1 = 0.f, ksa2 = 0.f, ksa3 = 0.f;

    for (int r = 0; r < CHUNK / UROW; r++) {
        const int s = s0 + r * UROW;
        // cooperative load of 8 rows of k (with phi) and v
        {
            const size_t off = base + (size_t)(s + lrow) * (NH * DD) + lcol;
            if (isK) {
                float4 kk = *(const float4*)(K + off);
                kk.x = phi(kk.x); kk.y = phi(kk.y); kk.z = phi(kk.z); kk.w = phi(kk.w);
                *(float4*)&ks[lrow][lcol] = kk;
                ksa0 += kk.x; ksa1 += kk.y; ksa2 += kk.z; ksa3 += kk.w;
            } else {
                *(float4*)&vs[lrow][lcol] = *(const float4*)(V + off);
            }
        }
        __syncthreads();
        #pragma unroll
        for (int rr = 0; rr < UROW; rr++) {
            ulonglong2 kp = *(const ulonglong2*)&ks[rr][tx * 4];  // {d0,d1},{d2,d3} packed
            float4 v4 = *(const float4*)&vs[rr][ty * 4];
            u64 vd;
            vd = pk2(v4.x); fma2(acc[0][0], kp.x, vd); fma2(acc[0][1], kp.y, vd);
            vd = pk2(v4.y); fma2(acc[1][0], kp.x, vd); fma2(acc[1][1], kp.y, vd);
            vd = pk2(v4.z); fma2(acc[2][0], kp.x, vd); fma2(acc[2][1], kp.y, vd);
            vd = pk2(v4.w); fma2(acc[3][0], kp.x, vd); fma2(acc[3][1], kp.y, vd);
        }
        __syncthreads();
    }

    // epilogue: g_kv layout [pair][d][m]
    float* kvp = g_kv + (size_t)pair * DD * DD;
    const int d0 = tx * 4, m0 = ty * 4;
    #pragma unroll
    for (int j = 0; j < 4; j++) {
        float a, bb;
        unpk(acc[j][0], a, bb);
        atomicAdd(kvp + (d0 + 0) * DD + m0 + j, a);
        atomicAdd(kvp + (d0 + 1) * DD + m0 + j, bb);
        unpk(acc[j][1], a, bb);
        atomicAdd(kvp + (d0 + 2) * DD + m0 + j, a);
        atomicAdd(kvp + (d0 + 3) * DD + m0 + j, bb);
    }
    if (isK) {
        float* ksp = g_ksum + pair * DD + lcol;
        atomicAdd(ksp + 0, ksa0);
        atomicAdd(ksp + 1, ksa1);
        atomicAdd(ksp + 2, ksa2);
        atomicAdd(ksp + 3, ksa3);
    }
}

// ---------------------------------------------------------------------------
// Kernel 2: out[l][m] = sum_d (z_l * phi(q[l,d])) * KV[d][m]
// grid (LL/128, NPAIR), 256 threads. Thread tile: 8 l x 4 m (2 f32x2).
#define TL 128
__global__ __launch_bounds__(256, 2)
void out_kernel(const float* __restrict__ Q, float* __restrict__ O) {
    __shared__ __align__(16) float qs[TL][DD];    // 32 KB : z-scaled phi(q)
    __shared__ __align__(16) float kvt[DD][DD];   // 16 KB : KV [d][m]

    const int pair = blockIdx.y;
    const int b = pair >> 3, hh = pair & 7;
    const int l0 = blockIdx.x * TL;
    const int tid = threadIdx.x;

    if (tid < TL) {
        // one q row per thread: phi, dot with ksum, scale by z, store to smem
        const int l = l0 + tid;
        const float* qrow = Q + ((size_t)(b * LL + l) * NH + hh) * DD;
        const float* ksg = g_ksum + pair * DD;
        float accz = 0.f;
        #pragma unroll
        for (int i = 0; i < 16; i++) {
            float4 q4 = *(const float4*)(qrow + i * 4);
            q4.x = phi(q4.x); q4.y = phi(q4.y); q4.z = phi(q4.z); q4.w = phi(q4.w);
            *(float4*)&qs[tid][i * 4] = q4;
            accz += q4.x * ksg[i * 4 + 0] + q4.y * ksg[i * 4 + 1]
                  + q4.z * ksg[i * 4 + 2] + q4.w * ksg[i * 4 + 3];
        }
        const float z = 1.f / (accz + 1e-6f);
        #pragma unroll
        for (int i = 0; i < 16; i++) {
            float4 t = *(const float4*)&qs[tid][i * 4];
            t.x *= z; t.y *= z; t.z *= z; t.w *= z;
            *(float4*)&qs[tid][i * 4] = t;
        }
    } else {
        // straight copy of KV (already [d][m]) — coalesced, conflict-free
        const int t = tid - 128;
        const float* kvsrc = g_kv + (size_t)pair * DD * DD;
        float* kvdst = &kvt[0][0];
        #pragma unroll
        for (int i = 0; i < 32; i++) {
            int idx = i * 128 + t;
            kvdst[idx] = kvsrc[idx];
        }
    }
    __syncthreads();

    const int tx = tid & 15;          // m0 = tx*4
    const int ty = tid >> 4;          // l rows ty*8 .. ty*8+7
    const int m0 = tx * 4;

    u64 acc[8][2];
    #pragma unroll
    for (int j = 0; j < 8; j++) { acc[j][0] = 0ull; acc[j][1] = 0ull; }

    #pragma unroll 4
    for (int d = 0; d < DD; d++) {
        ulonglong2 kp = *(const ulonglong2*)&kvt[d][m0];   // {m0,m1},{m2,m3}
        #pragma unroll
        for (int j = 0; j < 8; j++) {
            u64 qd = pk2(qs[ty * 8 + j][d]);
            fma2(acc[j][0], qd, kp.x);
            fma2(acc[j][1], qd, kp.y);
        }
    }

    // store: out [pair][l][m]
    #pragma unroll
    for (int j = 0; j < 8; j++) {
        const int l = l0 + ty * 8 + j;
        float4 o;
        unpk(acc[j][0], o.x, o.y);
        unpk(acc[j][1], o.z, o.w);
        *(float4*)(O + ((size_t)pair * LL + l) * DD + m0) = o;
    }
}

// ---------------------------------------------------------------------------
extern "C" void kernel_launch(void* const* d_in, const int* in_sizes, int n_in,
                              void* d_out, int out_size) {
    const float* Q = (const float*)d_in[0];
    const float* K = (const float*)d_in[1];
    const float* V = (const float*)d_in[2];
    float* O = (float*)d_out;

    zero_scratch<<<(NPAIR * DD * DD + 255) / 256, 256>>>();
    kv_kernel<<<dim3(SPL, NPAIR), 256>>>(K, V);
    out_kernel<<<dim3(LL / TL, NPAIR), 256>>>(Q, O);
}

// round 3
// speedup vs baseline: 1.9903x; 1.9903x over previous
#include <cuda_runtime.h>
#include <cstdint>

// LinearAttention n=4, L=8192, h=8, d=m=64 — mma.sync tf32 (sm_80 path, compiles on sm_103).
// out[pair,l,m] = z_l * sum_d phiQ[l,d] * KV[d,m]
// KV[d,m] = sum_s phiK[s,d] V[s,m];  z_l = 1/(phiQ[l,:]·ksum + 1e-6)

#define NB 4
#define LL 8192
#define NH 8
#define DD 64
#define NPAIR 32
#define SPL 16
#define CHUNK (LL / SPL)       // 512
#define ROWS 32                // s rows per smem round
#define NRND (CHUNK / ROWS)    // 16
#define PAD 72                 // floats per padded row (conflict-free fragments)
#define TLQ 128

__device__ float g_kv_part[SPL * NPAIR * DD * DD];   // 8 MB
__device__ float g_ksum_part[SPL * NPAIR * DD];
__device__ float g_kv[NPAIR * DD * DD];
__device__ float g_ksum[NPAIR * DD];

// ---------------- helpers ----------------
__device__ __forceinline__ uint32_t s2u(const void* p) {
    uint32_t a;
    asm("{ .reg .u64 t; cvta.to.shared.u64 t, %1; cvt.u32.u64 %0, t; }" : "=r"(a) : "l"(p));
    return a;
}
__device__ __forceinline__ uint32_t totf(float f) {
    uint32_t r; asm("cvt.rna.tf32.f32 %0, %1;" : "=r"(r) : "f"(f)); return r;
}
__device__ __forceinline__ float phi(float x) {
    x *= 0.35355339059327378f;            // 64^-0.25
    return x > 0.f ? x + 1.f : __expf(x);
}
__device__ __forceinline__ void mma8(float c[4], uint32_t a0, uint32_t a1,
                                     uint32_t a2, uint32_t a3,
                                     uint32_t b0, uint32_t b1) {
    asm volatile(
        "mma.sync.aligned.m16n8k8.row.col.f32.tf32.tf32.f32 "
        "{%0,%1,%2,%3}, {%4,%5,%6,%7}, {%8,%9}, {%0,%1,%2,%3};"
        : "+f"(c[0]), "+f"(c[1]), "+f"(c[2]), "+f"(c[3])
        : "r"(a0), "r"(a1), "r"(a2), "r"(a3), "r"(b0), "r"(b1));
}
__device__ __forceinline__ void cp16(uint32_t dst, const void* src) {
    asm volatile("cp.async.cg.shared.global [%0], [%1], 16;"
                 :: "r"(dst), "l"(src) : "memory");
}
#define CP_COMMIT() asm volatile("cp.async.commit_group;" ::: "memory")
#define CP_WAIT(N)  asm volatile("cp.async.wait_group %0;" :: "n"(N) : "memory")

// ---------------- kernel 1: KV partials ----------------
__global__ __launch_bounds__(256)
void kv_kernel(const float* __restrict__ K, const float* __restrict__ V) {
    __shared__ float Ks[2][ROWS][PAD];   // raw K (phi applied at fragment load)
    __shared__ float Vs[2][ROWS][PAD];

    const int tid = threadIdx.x, warp = tid >> 5, lane = tid & 31;
    const int gid = lane >> 2, tig = lane & 3;
    const int pair = blockIdx.y, b = pair >> 3, hh = pair & 7;
    const int split = blockIdx.x;
    const int wd = warp & 3, wm = warp >> 2;
    const int d0 = wd * 16, m0 = wm * 32;

    const size_t rstr = (size_t)NH * DD;
    const int lrow = tid >> 3, lcol = (tid & 7) * 8;
    const float* Kp = K + ((size_t)b * LL + split * CHUNK + lrow) * rstr + hh * DD + lcol;
    const float* Vp = V + ((size_t)b * LL + split * CHUNK + lrow) * rstr + hh * DD + lcol;
    const uint32_t kdst = s2u(&Ks[0][lrow][lcol]);
    const uint32_t vdst = s2u(&Vs[0][lrow][lcol]);
    const uint32_t bufB = ROWS * PAD * 4;   // 9216

    float acc[4][4];
    #pragma unroll
    for (int i = 0; i < 4; i++)
        #pragma unroll
        for (int j = 0; j < 4; j++) acc[i][j] = 0.f;
    float ks_lo = 0.f, ks_hi = 0.f;

    // prefetch round 0
    {
        cp16(kdst, Kp);       cp16(kdst + 16, Kp + 4);
        cp16(vdst, Vp);       cp16(vdst + 16, Vp + 4);
        CP_COMMIT();
    }

    for (int r = 0; r < NRND; r++) {
        if (r + 1 < NRND) {
            const size_t go = (size_t)(r + 1) * ROWS * rstr;
            const uint32_t so = ((r + 1) & 1) * bufB;
            cp16(kdst + so, Kp + go);      cp16(kdst + so + 16, Kp + go + 4);
            cp16(vdst + so, Vp + go);      cp16(vdst + so + 16, Vp + go + 4);
            CP_COMMIT();
            CP_WAIT(1);
        } else {
            CP_WAIT(0);
        }
        __syncthreads();

        const int buf = r & 1;
        #pragma unroll
        for (int ks = 0; ks < 4; ks++) {
            const int sb = ks * 8;
            float p00 = phi(Ks[buf][sb + tig][d0 + gid]);
            float p10 = phi(Ks[buf][sb + tig][d0 + gid + 8]);
            float p01 = phi(Ks[buf][sb + tig + 4][d0 + gid]);
            float p11 = phi(Ks[buf][sb + tig + 4][d0 + gid + 8]);
            if (wm == 0) { ks_lo += p00 + p01; ks_hi += p10 + p11; }
            const uint32_t a0 = totf(p00), a1 = totf(p10);
            const uint32_t a2 = totf(p01), a3 = totf(p11);
            #pragma unroll
            for (int nt = 0; nt < 4; nt++) {
                const int m = m0 + nt * 8 + gid;
                const uint32_t b0 = totf(Vs[buf][sb + tig][m]);
                const uint32_t b1 = totf(Vs[buf][sb + tig + 4][m]);
                mma8(acc[nt], a0, a1, a2, a3, b0, b1);
            }
        }
        __syncthreads();
    }

    // epilogue: partial KV tile -> gmem (no atomics)
    float* dst = g_kv_part + ((size_t)split * NPAIR + pair) * DD * DD;
    const int dlo = d0 + gid;
    #pragma unroll
    for (int nt = 0; nt < 4; nt++) {
        const int m = m0 + nt * 8 + 2 * tig;
        *(float2*)(dst + dlo * DD + m)       = make_float2(acc[nt][0], acc[nt][1]);
        *(float2*)(dst + (dlo + 8) * DD + m) = make_float2(acc[nt][2], acc[nt][3]);
    }
    if (wm == 0) {
        ks_lo += __shfl_xor_sync(0xffffffffu, ks_lo, 1);
        ks_lo += __shfl_xor_sync(0xffffffffu, ks_lo, 2);
        ks_hi += __shfl_xor_sync(0xffffffffu, ks_hi, 1);
        ks_hi += __shfl_xor_sync(0xffffffffu, ks_hi, 2);
        if (tig == 0) {
            float* kd = g_ksum_part + ((size_t)split * NPAIR + pair) * DD;
            kd[d0 + gid] = ks_lo;
            kd[d0 + gid + 8] = ks_hi;
        }
    }
}

// ---------------- reduce partials ----------------
__global__ void reduce_kernel() {
    const int i = blockIdx.x * blockDim.x + threadIdx.x;
    if (i < NPAIR * DD * DD) {
        float s = 0.f;
        #pragma unroll
        for (int p = 0; p < SPL; p++) s += g_kv_part[(size_t)p * NPAIR * DD * DD + i];
        g_kv[i] = s;
    } else {
        const int j = i - NPAIR * DD * DD;
        if (j < NPAIR * DD) {
            float s = 0.f;
            #pragma unroll
            for (int p = 0; p < SPL; p++) s += g_ksum_part[p * NPAIR * DD + j];
            g_ksum[j] = s;
        }
    }
}

// ---------------- kernel 2: output GEMM ----------------
// dynamic smem: qs[128][72] + kvs[64][72] + ksum[64]
#define K2_SMEM ((TLQ * PAD + DD * PAD + DD) * 4)

__global__ __launch_bounds__(256)
void out_kernel(const float* __restrict__ Q, float* __restrict__ O) {
    extern __shared__ float sm2[];
    float (*qs)[PAD]  = (float(*)[PAD])sm2;
    float (*kvs)[PAD] = (float(*)[PAD])(sm2 + TLQ * PAD);
    float* ksum_s = sm2 + TLQ * PAD + DD * PAD;

    const int tid = threadIdx.x, warp = tid >> 5, lane = tid & 31;
    const int gid = lane >> 2, tig = lane & 3;
    const int pair = blockIdx.y, b = pair >> 3, hh = pair & 7;
    const int l0 = blockIdx.x * TLQ;

    // ksum + KV (tf32) into smem
    if (tid < DD) ksum_s[tid] = g_ksum[pair * DD + tid];
    {
        const float* kvp = g_kv + (size_t)pair * DD * DD;
        #pragma unroll
        for (int k = 0; k < 4; k++) {
            const int f = (k * 256 + tid) * 4;
            const int d = f >> 6, m = f & 63;
            float4 v = *(const float4*)(kvp + f);
            float4 t;
            t.x = __uint_as_float(totf(v.x)); t.y = __uint_as_float(totf(v.y));
            t.z = __uint_as_float(totf(v.z)); t.w = __uint_as_float(totf(v.w));
            *(float4*)&kvs[d][m] = t;
        }
    }
    __syncthreads();

    // q prep: 2 threads per row (32 d each): phi, dot, z, scale, tf32
    {
        const int l = tid >> 1, half = tid & 1;
        const float* qrow = Q + ((size_t)b * LL + l0 + l) * (NH * DD)
                              + (size_t)hh * DD + half * 32;
        float accz = 0.f;
        #pragma unroll
        for (int i = 0; i < 8; i++) {
            float4 q4 = *(const float4*)(qrow + i * 4);
            q4.x = phi(q4.x); q4.y = phi(q4.y); q4.z = phi(q4.z); q4.w = phi(q4.w);
            const int c = half * 32 + i * 4;
            accz += q4.x * ksum_s[c] + q4.y * ksum_s[c + 1]
                  + q4.z * ksum_s[c + 2] + q4.w * ksum_s[c + 3];
            *(float4*)&qs[l][c] = q4;   // raw phi, scaled below
        }
        accz += __shfl_xor_sync(0xffffffffu, accz, 1);
        const float z = 1.f / (accz + 1e-6f);
        #pragma unroll
        for (int i = 0; i < 8; i++) {
            const int c = half * 32 + i * 4;
            float4 t = *(float4*)&qs[l][c];
            t.x = __uint_as_float(totf(t.x * z));
            t.y = __uint_as_float(totf(t.y * z));
            t.z = __uint_as_float(totf(t.z * z));
            t.w = __uint_as_float(totf(t.w * z));
            *(float4*)&qs[l][c] = t;
        }
    }
    __syncthreads();

    // 16l x 64m per warp
    const int lw0 = warp * 16;
    float acc[8][4];
    #pragma unroll
    for (int i = 0; i < 8; i++)
        #pragma unroll
        for (int j = 0; j < 4; j++) acc[i][j] = 0.f;

    #pragma unroll
    for (int kk = 0; kk < 8; kk++) {
        const int k0 = kk * 8;
        const uint32_t a0 = __float_as_uint(qs[lw0 + gid][k0 + tig]);
        const uint32_t a1 = __float_as_uint(qs[lw0 + gid + 8][k0 + tig]);
        const uint32_t a2 = __float_as_uint(qs[lw0 + gid][k0 + tig + 4]);
        const uint32_t a3 = __float_as_uint(qs[lw0 + gid + 8][k0 + tig + 4]);
        #pragma unroll
        for (int nt = 0; nt < 8; nt++) {
            const int m = nt * 8 + gid;
            const uint32_t b0 = __float_as_uint(kvs[k0 + tig][m]);
            const uint32_t b1 = __float_as_uint(kvs[k0 + tig + 4][m]);
            mma8(acc[nt], a0, a1, a2, a3, b0, b1);
        }
    }

    float* dst = O + ((size_t)pair * LL + l0 + lw0 + gid) * DD;
    #pragma unroll
    for (int nt = 0; nt < 8; nt++) {
        const int m = nt * 8 + 2 * tig;
        *(float2*)(dst + m)          = make_float2(acc[nt][0], acc[nt][1]);
        *(float2*)(dst + 8 * DD + m) = make_float2(acc[nt][2], acc[nt][3]);
    }
}

// ---------------- launch ----------------
extern "C" void kernel_launch(void* const* d_in, const int* in_sizes, int n_in,
                              void* d_out, int out_size) {
    const float* Q = (const float*)d_in[0];
    const float* K = (const float*)d_in[1];
    const float* V = (const float*)d_in[2];
    float* O = (float*)d_out;

    cudaFuncSetAttribute(out_kernel, cudaFuncAttributeMaxDynamicSharedMemorySize, K2_SMEM);

    kv_kernel<<<dim3(SPL, NPAIR), 256>>>(K, V);
    reduce_kernel<<<(NPAIR * DD * DD + NPAIR * DD + 255) / 256, 256>>>();
    out_kernel<<<dim3(LL / TLQ, NPAIR), 256, K2_SMEM>>>(Q, O);
}

// round 4
// speedup vs baseline: 2.1869x; 1.0988x over previous
#include <cuda_runtime.h>
#include <cstdint>

// LinearAttention n=4, L=8192, h=8, d=m=64 — mma.sync tf32, staging-hoisted phi/cvt.
// out[pair,l,m] = z_l * sum_d phiQ[l,d] * KV[d,m]
// KV[d,m] = sum_s phiK[s,d] V[s,m];  z_l = 1/(phiQ[l,:]·ksum + 1e-6)

#define NB 4
#define LL 8192
#define NH 8
#define DD 64
#define NPAIR 32
#define SPL 32
#define CHUNK (LL / SPL)       // 256
#define ROWS 32                // s rows per smem round
#define NRND (CHUNK / ROWS)    // 8
#define PADA 68                // gid-major-row access pattern (out qs)
#define PADB 72                // tig-major-row access pattern (Ks/Vs/kvs)
#define TLQ 128

__device__ float g_kv_part[SPL * NPAIR * DD * DD];   // 16 MB
__device__ float g_ksum_part[SPL * NPAIR * DD];
__device__ float g_kv[NPAIR * DD * DD];              // tf32-rounded
__device__ float g_ksum[NPAIR * DD];                 // fp32

// ---------------- helpers ----------------
__device__ __forceinline__ uint32_t s2u(const void* p) {
    uint32_t a;
    asm("{ .reg .u64 t; cvta.to.shared.u64 t, %1; cvt.u32.u64 %0, t; }" : "=r"(a) : "l"(p));
    return a;
}
__device__ __forceinline__ uint32_t totf(float f) {
    uint32_t r; asm("cvt.rna.tf32.f32 %0, %1;" : "=r"(r) : "f"(f)); return r;
}
__device__ __forceinline__ float phi(float x) {
    x *= 0.35355339059327378f;            // 64^-0.25
    return x > 0.f ? x + 1.f : __expf(x);
}
__device__ __forceinline__ void mma8(float c[4], uint32_t a0, uint32_t a1,
                                     uint32_t a2, uint32_t a3,
                                     uint32_t b0, uint32_t b1) {
    asm volatile(
        "mma.sync.aligned.m16n8k8.row.col.f32.tf32.tf32.f32 "
        "{%0,%1,%2,%3}, {%4,%5,%6,%7}, {%8,%9}, {%0,%1,%2,%3};"
        : "+f"(c[0]), "+f"(c[1]), "+f"(c[2]), "+f"(c[3])
        : "r"(a0), "r"(a1), "r"(a2), "r"(a3), "r"(b0), "r"(b1));
}
__device__ __forceinline__ void cp16(uint32_t dst, const void* src) {
    asm volatile("cp.async.cg.shared.global [%0], [%1], 16;"
                 :: "r"(dst), "l"(src) : "memory");
}
#define CP_COMMIT() asm volatile("cp.async.commit_group;" ::: "memory")
#define CP_WAIT(N)  asm volatile("cp.async.wait_group %0;" :: "n"(N) : "memory")

// ---------------- kernel 1: KV partials ----------------
__global__ __launch_bounds__(256)
void kv_kernel(const float* __restrict__ K, const float* __restrict__ V) {
    __shared__ float Ks[ROWS][PADB];      // tf32-converted phi(K)
    __shared__ float Vs[2][ROWS][PADB];   // raw fp32 V (fed as tf32 bits)
    __shared__ float ksum_s[DD];

    const int tid = threadIdx.x, warp = tid >> 5, lane = tid & 31;
    const int gid = lane >> 2, tig = lane & 3;
    const int pair = blockIdx.y, b = pair >> 3, hh = pair & 7;
    const int split = blockIdx.x;
    const int wd = warp & 3, wm = warp >> 2;
    const int d0 = wd * 16, m0 = wm * 32;

    const size_t rstr = (size_t)NH * DD;
    const int lrow = tid >> 3, lcg = tid & 7, lcol = lcg * 8;
    const float* Kp = K + ((size_t)b * LL + split * CHUNK + lrow) * rstr + hh * DD + lcol;
    const float* Vp = V + ((size_t)b * LL + split * CHUNK + lrow) * rstr + hh * DD + lcol;
    const uint32_t vdst = s2u(&Vs[0][lrow][lcol]);
    const uint32_t bufB = ROWS * PADB * 4;   // 9216

    if (tid < DD) ksum_s[tid] = 0.f;

    float acc[4][4];
    #pragma unroll
    for (int i = 0; i < 4; i++)
        #pragma unroll
        for (int j = 0; j < 4; j++) acc[i][j] = 0.f;
    float ks[8];
    #pragma unroll
    for (int j = 0; j < 8; j++) ks[j] = 0.f;

    // prologue: prefetch V(0) + K(0)
    cp16(vdst, Vp); cp16(vdst + 16, Vp + 4);
    CP_COMMIT();
    float4 ka = *(const float4*)Kp;
    float4 kb = *(const float4*)(Kp + 4);

    #pragma unroll
    for (int r = 0; r < NRND; r++) {
        if (r + 1 < NRND) {
            const size_t go = (size_t)(r + 1) * ROWS * rstr;
            const uint32_t so = ((r + 1) & 1) * bufB;
            cp16(vdst + so, Vp + go); cp16(vdst + so + 16, Vp + go + 4);
            CP_COMMIT();
        }
        // stage K: phi + ksum + tf32 cvt, once per element
        {
            float p[8];
            p[0] = phi(ka.x); p[1] = phi(ka.y); p[2] = phi(ka.z); p[3] = phi(ka.w);
            p[4] = phi(kb.x); p[5] = phi(kb.y); p[6] = phi(kb.z); p[7] = phi(kb.w);
            #pragma unroll
            for (int j = 0; j < 8; j++) ks[j] += p[j];
            uint4 u0, u1;
            u0.x = totf(p[0]); u0.y = totf(p[1]); u0.z = totf(p[2]); u0.w = totf(p[3]);
            u1.x = totf(p[4]); u1.y = totf(p[5]); u1.z = totf(p[6]); u1.w = totf(p[7]);
            *(uint4*)&Ks[lrow][lcol]     = u0;
            *(uint4*)&Ks[lrow][lcol + 4] = u1;
        }
        if (r + 1 < NRND) {
            const size_t go = (size_t)(r + 1) * ROWS * rstr;
            ka = *(const float4*)(Kp + go);
            kb = *(const float4*)(Kp + go + 4);
            CP_WAIT(1);
        } else {
            CP_WAIT(0);
        }
        __syncthreads();

        const int buf = r & 1;
        #pragma unroll
        for (int kstp = 0; kstp < 4; kstp++) {
            const int sb = kstp * 8;
            const uint32_t a0 = __float_as_uint(Ks[sb + tig][d0 + gid]);
            const uint32_t a1 = __float_as_uint(Ks[sb + tig][d0 + gid + 8]);
            const uint32_t a2 = __float_as_uint(Ks[sb + tig + 4][d0 + gid]);
            const uint32_t a3 = __float_as_uint(Ks[sb + tig + 4][d0 + gid + 8]);
            #pragma unroll
            for (int nt = 0; nt < 4; nt++) {
                const int m = m0 + nt * 8 + gid;
                const uint32_t b0 = __float_as_uint(Vs[buf][sb + tig][m]);
                const uint32_t b1 = __float_as_uint(Vs[buf][sb + tig + 4][m]);
                mma8(acc[nt], a0, a1, a2, a3, b0, b1);
            }
        }
        __syncthreads();
    }

    // epilogue: partial KV tile -> gmem
    float* dst = g_kv_part + ((size_t)split * NPAIR + pair) * DD * DD;
    const int dlo = d0 + gid;
    #pragma unroll
    for (int nt = 0; nt < 4; nt++) {
        const int m = m0 + nt * 8 + 2 * tig;
        *(float2*)(dst + dlo * DD + m)       = make_float2(acc[nt][0], acc[nt][1]);
        *(float2*)(dst + (dlo + 8) * DD + m) = make_float2(acc[nt][2], acc[nt][3]);
    }
    // ksum: reduce 4 rows within warp, then 8-way atomic across warps
    #pragma unroll
    for (int j = 0; j < 8; j++) {
        ks[j] += __shfl_xor_sync(0xffffffffu, ks[j], 8);
        ks[j] += __shfl_xor_sync(0xffffffffu, ks[j], 16);
    }
    if (lane < 8) {
        #pragma unroll
        for (int j = 0; j < 8; j++)
            atomicAdd(&ksum_s[lane * 8 + j], ks[j]);
    }
    __syncthreads();
    if (tid < DD)
        g_ksum_part[((size_t)split * NPAIR + pair) * DD + tid] = ksum_s[tid];
}

// ---------------- reduce partials (KV -> tf32, ksum -> fp32) ----------------
__global__ void reduce_kernel() {
    const int i = blockIdx.x * blockDim.x + threadIdx.x;
    if (i < NPAIR * DD * DD) {
        float s = 0.f;
        #pragma unroll
        for (int p = 0; p < SPL; p++) s += g_kv_part[(size_t)p * NPAIR * DD * DD + i];
        g_kv[i] = __uint_as_float(totf(s));
    } else {
        const int j = i - NPAIR * DD * DD;
        if (j < NPAIR * DD) {
            float s = 0.f;
            #pragma unroll
            for (int p = 0; p < SPL; p++) s += g_ksum_part[p * NPAIR * DD + j];
            g_ksum[j] = s;
        }
    }
}

// ---------------- kernel 2: output GEMM ----------------
// dynamic smem: qs[128][PADA] + kvs[64][PADB] + ksum[64]
#define K2_SMEM ((TLQ * PADA + DD * PADB + DD) * 4)

__global__ __launch_bounds__(256)
void out_kernel(const float* __restrict__ Q, float* __restrict__ O) {
    extern __shared__ float sm2[];
    float (*qs)[PADA]  = (float(*)[PADA])sm2;
    float (*kvs)[PADB] = (float(*)[PADB])(sm2 + TLQ * PADA);
    float* ksum_s = sm2 + TLQ * PADA + DD * PADB;

    const int tid = threadIdx.x, warp = tid >> 5, lane = tid & 31;
    const int gid = lane >> 2, tig = lane & 3;
    const int pair = blockIdx.y, b = pair >> 3, hh = pair & 7;
    const int l0 = blockIdx.x * TLQ;

    // ksum + KV (already tf32) into smem
    if (tid < DD) ksum_s[tid] = g_ksum[pair * DD + tid];
    {
        const float* kvp = g_kv + (size_t)pair * DD * DD;
        #pragma unroll
        for (int k = 0; k < 4; k++) {
            const int f = (k * 256 + tid) * 4;
            *(float4*)&kvs[f >> 6][f & 63] = *(const float4*)(kvp + f);
        }
    }
    __syncthreads();

    // q prep: 2 threads per row: phi, dot(ksum), z, scale, tf32
    {
        const int l = tid >> 1, half = tid & 1;
        const float* qrow = Q + ((size_t)b * LL + l0 + l) * (NH * DD)
                              + (size_t)hh * DD + half * 32;
        float4 qv[8];
        float accz = 0.f;
        #pragma unroll
        for (int i = 0; i < 8; i++) {
            float4 q4 = *(const float4*)(qrow + i * 4);
            q4.x = phi(q4.x); q4.y = phi(q4.y); q4.z = phi(q4.z); q4.w = phi(q4.w);
            const int c = half * 32 + i * 4;
            accz += q4.x * ksum_s[c] + q4.y * ksum_s[c + 1]
                  + q4.z * ksum_s[c + 2] + q4.w * ksum_s[c + 3];
            qv[i] = q4;
        }
        accz += __shfl_xor_sync(0xffffffffu, accz, 1);
        const float z = 1.f / (accz + 1e-6f);
        #pragma unroll
        for (int i = 0; i < 8; i++) {
            uint4 u;
            u.x = totf(qv[i].x * z); u.y = totf(qv[i].y * z);
            u.z = totf(qv[i].z * z); u.w = totf(qv[i].w * z);
            *(uint4*)&qs[l][half * 32 + i * 4] = u;
        }
    }
    __syncthreads();

    // 32l x 32m per warp
    const int l0w = (warp & 3) * 32;
    const int m0  = (warp >> 2) * 32;
    float acc[2][4][4];
    #pragma unroll
    for (int lt = 0; lt < 2; lt++)
        #pragma unroll
        for (int i = 0; i < 4; i++)
            #pragma unroll
            for (int j = 0; j < 4; j++) acc[lt][i][j] = 0.f;

    #pragma unroll
    for (int kk = 0; kk < 8; kk++) {
        const int k0 = kk * 8;
        uint32_t a[2][4];
        #pragma unroll
        for (int lt = 0; lt < 2; lt++) {
            const int row = l0w + lt * 16;
            a[lt][0] = __float_as_uint(qs[row + gid][k0 + tig]);
            a[lt][1] = __float_as_uint(qs[row + gid + 8][k0 + tig]);
            a[lt][2] = __float_as_uint(qs[row + gid][k0 + tig + 4]);
            a[lt][3] = __float_as_uint(qs[row + gid + 8][k0 + tig + 4]);
        }
        #pragma unroll
        for (int nt = 0; nt < 4; nt++) {
            const int m = m0 + nt * 8 + gid;
            const uint32_t b0 = __float_as_uint(kvs[k0 + tig][m]);
            const uint32_t b1 = __float_as_uint(kvs[k0 + tig + 4][m]);
            mma8(acc[0][nt], a[0][0], a[0][1], a[0][2], a[0][3], b0, b1);
            mma8(acc[1][nt], a[1][0], a[1][1], a[1][2], a[1][3], b0, b1);
        }
    }

    #pragma unroll
    for (int lt = 0; lt < 2; lt++) {
        float* dst = O + ((size_t)pair * LL + l0 + l0w + lt * 16 + gid) * DD;
        #pragma unroll
        for (int nt = 0; nt < 4; nt++) {
            const int m = m0 + nt * 8 + 2 * tig;
            *(float2*)(dst + m)          = make_float2(acc[lt][nt][0], acc[lt][nt][1]);
            *(float2*)(dst + 8 * DD + m) = make_float2(acc[lt][nt][2], acc[lt][nt][3]);
        }
    }
}

// ---------------- launch ----------------
extern "C" void kernel_launch(void* const* d_in, const int* in_sizes, int n_in,
                              void* d_out, int out_size) {
    const float* Q = (const float*)d_in[0];
    const float* K = (const float*)d_in[1];
    const float* V = (const float*)d_in[2];
    float* O = (float*)d_out;

    cudaFuncSetAttribute(out_kernel, cudaFuncAttributeMaxDynamicSharedMemorySize, K2_SMEM);

    kv_kernel<<<dim3(SPL, NPAIR), 256>>>(K, V);
    reduce_kernel<<<(NPAIR * DD * DD + NPAIR * DD + 255) / 256, 256>>>();
    out_kernel<<<dim3(LL / TLQ, NPAIR), 256, K2_SMEM>>>(Q, O);
}